// round 1
// baseline (speedup 1.0000x reference)
#include <cuda_runtime.h>
#include <cstdint>

// Problem constants
namespace {
constexpr int NB = 4;          // batch
constexpr int NL = 2048;       // sequence length
constexpr int ND = 1024;       // model dim
constexpr int NH = 16;         // heads
constexpr int NDK = 64;        // head dim
constexpr int MROWS = NB * NL;     // 8192
constexpr int NQKV = 3 * ND;       // 3072
}

// Scratch (device globals: allocation-free per harness rules)
__device__ float g_q[(size_t)NB * NH * NL * NDK];   // (B,H,L,DK), pre-scaled by 1/sqrt(DK)
__device__ float g_k[(size_t)NB * NH * NL * NDK];
__device__ float g_v[(size_t)NB * NH * NL * NDK];
__device__ float g_ctx[(size_t)NB * NL * ND];       // (B,L,D)

// ---------------------------------------------------------------------------
// Tiled fp32 SGEMM: C(MxN) = A(MxK) @ Bm(KxN) + bias
// MODE 0: write C = A@B + bias (row-major)
// MODE 1: scatter into g_q/g_k/g_v (QKV epilogue), scale Q by 0.125
// BM=BN=128, BK=8, 256 threads, 8x8 register micro-tile per thread.
// ---------------------------------------------------------------------------
template <int MODE>
__global__ __launch_bounds__(256) void sgemm_kernel(
    const float* __restrict__ A, const float* __restrict__ Bm,
    const float* __restrict__ bias, float* __restrict__ C,
    int M, int N, int K)
{
    constexpr int BM = 128, BN = 128, BK = 8;
    __shared__ float As[BK][BM];   // transposed A tile
    __shared__ float Bs[BK][BN];

    const int tid = threadIdx.x;
    const int rowBase = blockIdx.y * BM;
    const int colBase = blockIdx.x * BN;
    const int tr = tid / 16;        // 0..15
    const int tc = tid % 16;        // 0..15

    const int aRow = tid >> 1;            // 0..127
    const int aCol = (tid & 1) * 4;       // 0 or 4
    const int bRow = tid >> 5;            // 0..7
    const int bCol = (tid & 31) * 4;      // 0..124

    const float* Aptr = A + (size_t)(rowBase + aRow) * K + aCol;
    const float* Bptr = Bm + (size_t)bRow * N + colBase + bCol;

    float acc[8][8];
#pragma unroll
    for (int i = 0; i < 8; i++)
#pragma unroll
        for (int j = 0; j < 8; j++) acc[i][j] = 0.0f;

    float4 a4 = *(const float4*)Aptr;  Aptr += BK;
    float4 b4 = *(const float4*)Bptr;  Bptr += (size_t)BK * N;

    for (int kt = 0; kt < K; kt += BK) {
        As[aCol + 0][aRow] = a4.x;
        As[aCol + 1][aRow] = a4.y;
        As[aCol + 2][aRow] = a4.z;
        As[aCol + 3][aRow] = a4.w;
        *(float4*)&Bs[bRow][bCol] = b4;
        __syncthreads();

        if (kt + BK < K) {
            a4 = *(const float4*)Aptr;  Aptr += BK;
            b4 = *(const float4*)Bptr;  Bptr += (size_t)BK * N;
        }

#pragma unroll
        for (int kk = 0; kk < BK; kk++) {
            float ar[8], br[8];
            *(float4*)(ar)     = *(const float4*)&As[kk][tr * 8];
            *(float4*)(ar + 4) = *(const float4*)&As[kk][tr * 8 + 4];
            *(float4*)(br)     = *(const float4*)&Bs[kk][tc * 8];
            *(float4*)(br + 4) = *(const float4*)&Bs[kk][tc * 8 + 4];
#pragma unroll
            for (int i = 0; i < 8; i++)
#pragma unroll
                for (int j = 0; j < 8; j++)
                    acc[i][j] = fmaf(ar[i], br[j], acc[i][j]);
        }
        __syncthreads();
    }

    const int col0 = colBase + tc * 8;
    float bv[8];
#pragma unroll
    for (int j = 0; j < 8; j++) bv[j] = bias[col0 + j];

    if (MODE == 0) {
#pragma unroll
        for (int i = 0; i < 8; i++) {
            const int row = rowBase + tr * 8 + i;
            float* p = C + (size_t)row * N + col0;
            float4 o0, o1;
            o0.x = acc[i][0] + bv[0]; o0.y = acc[i][1] + bv[1];
            o0.z = acc[i][2] + bv[2]; o0.w = acc[i][3] + bv[3];
            o1.x = acc[i][4] + bv[4]; o1.y = acc[i][5] + bv[5];
            o1.z = acc[i][6] + bv[6]; o1.w = acc[i][7] + bv[7];
            *(float4*)p       = o0;
            *(float4*)(p + 4) = o1;
        }
    } else {
        // QKV scatter epilogue. 8 consecutive cols stay inside one (which,h) chunk.
        const int which = col0 / ND;            // 0=q, 1=k, 2=v
        const int rem   = col0 - which * ND;
        const int h     = rem / NDK;
        const int dk0   = rem - h * NDK;
        float* dst = (which == 0) ? g_q : (which == 1) ? g_k : g_v;
        const float scale = (which == 0) ? 0.125f : 1.0f;   // 1/sqrt(64)
#pragma unroll
        for (int i = 0; i < 8; i++) {
            const int row = rowBase + tr * 8 + i;
            const int bb = row >> 11;           // /L (2048)
            const int l  = row & (NL - 1);
            float* p = dst + (((size_t)(bb * NH + h) * NL + l) * NDK + dk0);
            float4 o0, o1;
            o0.x = (acc[i][0] + bv[0]) * scale; o0.y = (acc[i][1] + bv[1]) * scale;
            o0.z = (acc[i][2] + bv[2]) * scale; o0.w = (acc[i][3] + bv[3]) * scale;
            o1.x = (acc[i][4] + bv[4]) * scale; o1.y = (acc[i][5] + bv[5]) * scale;
            o1.z = (acc[i][6] + bv[6]) * scale; o1.w = (acc[i][7] + bv[7]) * scale;
            *(float4*)p       = o0;
            *(float4*)(p + 4) = o1;
        }
    }
}

// ---------------------------------------------------------------------------
// Fused attention: per (b,h), 64-query tiles, streaming over 64-key tiles.
// Semantics match the reference exactly:
//   val = mask ? score : 0.0  (masked fill underflows to 0.0 in fp32)
//   softmax over ALL 64·32 values per row (masked entries contribute exp(0-m))
//   numerator only over unmasked entries (attn re-zeroed where masked)
// Thread map: 256 threads = 64 queries x 4 lanes. Lane t owns dk = t*16..t*16+15.
// ---------------------------------------------------------------------------
constexpr int SMEM_ATTN_BYTES = (3 * 64 * 68 + 64 * 65) * 4;  // 68864 B

__global__ __launch_bounds__(256) void attn_kernel(const int* __restrict__ mask)
{
    extern __shared__ float sm[];
    float* Qs = sm;                 // [64][68]
    float* Ks = Qs + 64 * 68;       // [64][68]
    float* Vs = Ks + 64 * 68;       // [64][68]
    float* Ps = Vs + 64 * 68;       // [64][65]

    const int tid = threadIdx.x;
    const int qi = tid >> 2;        // 0..63 query within tile
    const int t  = tid & 3;         // lane within query group

    const int qt = blockIdx.x;      // query tile (0..31)
    const int bh = blockIdx.y;      // b*H + h   (0..63)
    const int b  = bh >> 4;
    const int h  = bh & 15;
    const int q0 = qt * 64;

    const float* Qg = g_q + ((size_t)bh * NL + q0) * NDK;
    const float* Kg = g_k + (size_t)bh * NL * NDK;
    const float* Vg = g_v + (size_t)bh * NL * NDK;
    const int* mrow = mask + ((size_t)b * NL + (q0 + qi)) * NL;

    // Load Q tile (coalesced float4)
#pragma unroll
    for (int v = 0; v < 4; v++) {
        const int lin = tid + v * 256;      // float4 index 0..1023
        const int r = lin >> 4;
        const int c = (lin & 15) * 4;
        float4 x = *(const float4*)(Qg + r * 64 + c);
        float* d = Qs + r * 68 + c;
        d[0] = x.x; d[1] = x.y; d[2] = x.z; d[3] = x.w;
    }

    float acc[16];
#pragma unroll
    for (int i = 0; i < 16; i++) acc[i] = 0.0f;
    float m_run = -1e30f;
    float d_run = 0.0f;

    for (int kt = 0; kt < NL / 64; kt++) {
        const int k0 = kt * 64;
        // Load K, V tiles
#pragma unroll
        for (int v = 0; v < 4; v++) {
            const int lin = tid + v * 256;
            const int r = lin >> 4;
            const int c = (lin & 15) * 4;
            float4 kx = *(const float4*)(Kg + (size_t)(k0 + r) * 64 + c);
            float4 vx = *(const float4*)(Vg + (size_t)(k0 + r) * 64 + c);
            float* dk = Ks + r * 68 + c;
            float* dv = Vs + r * 68 + c;
            dk[0] = kx.x; dk[1] = kx.y; dk[2] = kx.z; dk[3] = kx.w;
            dv[0] = vx.x; dv[1] = vx.y; dv[2] = vx.z; dv[3] = vx.w;
        }
        __syncthreads();

        // Scores: s[j] = Qrow . Krow(4j+t)   (Q pre-scaled by 1/sqrt(dk))
        float s[16];
#pragma unroll
        for (int j = 0; j < 16; j++) s[j] = 0.0f;
#pragma unroll 4
        for (int d4 = 0; d4 < 16; d4++) {
            float4 q4 = *(const float4*)&Qs[qi * 68 + d4 * 4];
#pragma unroll
            for (int j = 0; j < 16; j++) {
                const int kj = 4 * j + t;
                float4 k4 = *(const float4*)&Ks[kj * 68 + d4 * 4];
                s[j] = fmaf(q4.x, k4.x, s[j]);
                s[j] = fmaf(q4.y, k4.y, s[j]);
                s[j] = fmaf(q4.z, k4.z, s[j]);
                s[j] = fmaf(q4.w, k4.w, s[j]);
            }
        }

        // Mask (masked -> 0.0), tile max/sum over the 4-lane group
        const int* mp = mrow + k0;
        int mv[16];
        float vals[16];
        float tmax = -1e30f;
#pragma unroll
        for (int j = 0; j < 16; j++) {
            mv[j] = mp[4 * j + t];
            vals[j] = mv[j] ? s[j] : 0.0f;
            tmax = fmaxf(tmax, vals[j]);
        }
        tmax = fmaxf(tmax, __shfl_xor_sync(0xffffffffu, tmax, 1));
        tmax = fmaxf(tmax, __shfl_xor_sync(0xffffffffu, tmax, 2));
        const float m_new = fmaxf(m_run, tmax);

        float p[16];
        float psum = 0.0f;
#pragma unroll
        for (int j = 0; j < 16; j++) {
            p[j] = __expf(vals[j] - m_new);     // denominator includes masked(0.0) entries
            psum += p[j];
        }
        psum += __shfl_xor_sync(0xffffffffu, psum, 1);
        psum += __shfl_xor_sync(0xffffffffu, psum, 2);

        const float corr = __expf(m_run - m_new);
        d_run = d_run * corr + psum;
#pragma unroll
        for (int i = 0; i < 16; i++) acc[i] *= corr;
        m_run = m_new;

        // Numerator weights: zero where masked
#pragma unroll
        for (int j = 0; j < 16; j++)
            Ps[qi * 65 + 4 * j + t] = mv[j] ? p[j] : 0.0f;
        __syncthreads();

        // acc += P @ V  (lane t covers dk = t*16 .. t*16+15)
#pragma unroll 4
        for (int kj = 0; kj < 64; kj++) {
            const float pw = Ps[qi * 65 + kj];
#pragma unroll
            for (int g = 0; g < 4; g++) {
                float4 v4 = *(const float4*)&Vs[kj * 68 + t * 16 + g * 4];
                acc[g * 4 + 0] = fmaf(pw, v4.x, acc[g * 4 + 0]);
                acc[g * 4 + 1] = fmaf(pw, v4.y, acc[g * 4 + 1]);
                acc[g * 4 + 2] = fmaf(pw, v4.z, acc[g * 4 + 2]);
                acc[g * 4 + 3] = fmaf(pw, v4.w, acc[g * 4 + 3]);
            }
        }
        __syncthreads();   // protect Ks/Vs/Ps before next tile's loads
    }

    const float inv = 1.0f / d_run;
    float* op = g_ctx + ((size_t)(b * NL + q0 + qi) * ND) + h * NDK + t * 16;
#pragma unroll
    for (int g = 0; g < 4; g++) {
        float4 o;
        o.x = acc[g * 4 + 0] * inv;
        o.y = acc[g * 4 + 1] * inv;
        o.z = acc[g * 4 + 2] * inv;
        o.w = acc[g * 4 + 3] * inv;
        *(float4*)(op + g * 4) = o;
    }
}

// ---------------------------------------------------------------------------
extern "C" void kernel_launch(void* const* d_in, const int* in_sizes, int n_in,
                              void* d_out, int out_size)
{
    (void)in_sizes; (void)n_in; (void)out_size;
    const float* X    = (const float*)d_in[0];   // (B,L,D)
    const int*   mask = (const int*)d_in[1];     // (B,L,L)
    const float* W1   = (const float*)d_in[2];   // (D,3D)
    const float* b1   = (const float*)d_in[3];   // (3D)
    const float* W2   = (const float*)d_in[4];   // (D,D)
    const float* b2   = (const float*)d_in[5];   // (D)
    float* out = (float*)d_out;                  // (B,L,D)

    void* ctxPtr = nullptr;
    cudaGetSymbolAddress(&ctxPtr, g_ctx);
    cudaFuncSetAttribute(attn_kernel,
                         cudaFuncAttributeMaxDynamicSharedMemorySize,
                         SMEM_ATTN_BYTES);

    // 1) QKV projection + scatter
    sgemm_kernel<1><<<dim3(NQKV / 128, MROWS / 128), 256>>>(
        X, W1, b1, nullptr, MROWS, NQKV, ND);

    // 2) Fused masked attention -> g_ctx
    attn_kernel<<<dim3(NL / 64, NB * NH), 256, SMEM_ATTN_BYTES>>>(mask);

    // 3) Output projection
    sgemm_kernel<0><<<dim3(ND / 128, MROWS / 128), 256>>>(
        (const float*)ctxPtr, W2, b2, out, MROWS, ND, ND);
}

// round 4
// speedup vs baseline: 1.1418x; 1.1418x over previous
#include <cuda_runtime.h>
#include <cstdint>

// Problem constants
namespace {
constexpr int NB = 4;          // batch
constexpr int NL = 2048;       // sequence length
constexpr int ND = 1024;       // model dim
constexpr int NH = 16;         // heads
constexpr int NDK = 64;        // head dim
constexpr int MROWS = NB * NL;     // 8192
constexpr int NQKV = 3 * ND;       // 3072
}

// Scratch (device globals: allocation-free per harness rules)
__device__ float g_q[(size_t)NB * NH * NL * NDK];   // (B,H,L,DK), pre-scaled by 1/8
__device__ float g_k[(size_t)NB * NH * NL * NDK];
__device__ float g_v[(size_t)NB * NH * NL * NDK];
__device__ float g_ctx[(size_t)NB * NL * ND];       // (B,L,D)
__device__ float g_w1t[(size_t)NQKV * ND];          // W1^T (3D x D)
__device__ float g_w2t[(size_t)ND * ND];            // W2^T (D x D)

// ---------------------------------------------------------------------------
// Helpers
// ---------------------------------------------------------------------------
__device__ __forceinline__ uint32_t f2tf32(float x) {
    uint32_t r;
    asm("cvt.rna.tf32.f32 %0, %1;" : "=r"(r) : "f"(x));
    return r;
}
__device__ __forceinline__ void cp_async16(uint32_t saddr, const void* g) {
    asm volatile("cp.async.cg.shared.global [%0], [%1], 16;"
                 :: "r"(saddr), "l"(g));
}
__device__ __forceinline__ void cp_commit() {
    asm volatile("cp.async.commit_group;");
}
template <int N>
__device__ __forceinline__ void cp_wait() {
    asm volatile("cp.async.wait_group %0;" :: "n"(N));
}
__device__ __forceinline__ void mma_tf32_16n8k8(float* c, const uint32_t* a,
                                                const uint32_t* b) {
    asm volatile(
        "mma.sync.aligned.m16n8k8.row.col.f32.tf32.tf32.f32 "
        "{%0,%1,%2,%3}, {%4,%5,%6,%7}, {%8,%9}, {%0,%1,%2,%3};"
        : "+f"(c[0]), "+f"(c[1]), "+f"(c[2]), "+f"(c[3])
        : "r"(a[0]), "r"(a[1]), "r"(a[2]), "r"(a[3]), "r"(b[0]), "r"(b[1]));
}

// ---------------------------------------------------------------------------
// Transpose kernel: dst[c][r] = src[r][c], R x C -> C x R
// ---------------------------------------------------------------------------
__global__ void transpose_kernel(const float* __restrict__ src,
                                 float* __restrict__ dst, int R, int C) {
    __shared__ float t[32][33];
    const int c0 = blockIdx.x * 32, r0 = blockIdx.y * 32;
    const int x = threadIdx.x, y = threadIdx.y;  // 32 x 8
#pragma unroll
    for (int i = 0; i < 32; i += 8)
        t[y + i][x] = src[(size_t)(r0 + y + i) * C + c0 + x];
    __syncthreads();
#pragma unroll
    for (int i = 0; i < 32; i += 8)
        dst[(size_t)(c0 + y + i) * R + r0 + x] = t[x][y + i];
}

// ---------------------------------------------------------------------------
// TF32 mma.sync GEMM: D(MxN) = A(MxK) @ Bt(NxK)^T + bias
// CTA 128x128, BK=32, 8 warps (2x4), warp tile 64x32 = 4x4 m16n8k8 frags.
// cp.async double-buffered smem, padded rows (36 floats) for conflict-free
// fragment loads. MODE 0: row-major C. MODE 1: QKV scatter epilogue.
// ---------------------------------------------------------------------------
constexpr int BK = 32;
constexpr int ROWPAD = 36;                       // floats per smem row
constexpr int TILE_FLOATS = 128 * ROWPAD;        // 4608 floats per operand tile
constexpr int BUF_FLOATS = 2 * TILE_FLOATS;      // A + B
constexpr int GEMM_SMEM_BYTES = 2 * BUF_FLOATS * 4;   // 73728

template <int MODE>
__global__ __launch_bounds__(256)
void mma_gemm(const float* __restrict__ A, const float* __restrict__ Bt,
              const float* __restrict__ bias, float* __restrict__ C,
              int M, int N, int K)
{
    extern __shared__ float sm[];

    const int tid = threadIdx.x;
    const int wid = tid >> 5, lane = tid & 31;
    const int groupID = lane >> 2, tig = lane & 3;
    const int warp_m = (wid & 1) * 64;
    const int warp_n = (wid >> 1) * 32;
    const int rowBase = blockIdx.y * 128, colBase = blockIdx.x * 128;

    const uint32_t smem_base = (uint32_t)__cvta_generic_to_shared(sm);

    // Per-thread load mapping: 4 iters x 256 threads = 1024 16B slots per tile
    auto issue_chunk = [&](int buf, int k0) {
        const uint32_t a_s = smem_base + (uint32_t)(buf * BUF_FLOATS) * 4u;
        const uint32_t b_s = a_s + (uint32_t)TILE_FLOATS * 4u;
#pragma unroll
        for (int i = 0; i < 4; i++) {
            const int lin = tid + i * 256;
            const int r = lin >> 3, c = (lin & 7) * 4;
            const uint32_t so = (uint32_t)(r * ROWPAD + c) * 4u;
            cp_async16(a_s + so, A + (size_t)(rowBase + r) * K + k0 + c);
            cp_async16(b_s + so, Bt + (size_t)(colBase + r) * K + k0 + c);
        }
        cp_commit();
    };

    float acc[4][4][4];
#pragma unroll
    for (int mt = 0; mt < 4; mt++)
#pragma unroll
        for (int nt = 0; nt < 4; nt++)
#pragma unroll
            for (int i = 0; i < 4; i++) acc[mt][nt][i] = 0.0f;

    const int NK = K / BK;
    issue_chunk(0, 0);

    for (int kt = 0; kt < NK; kt++) {
        if (kt + 1 < NK) {
            issue_chunk((kt + 1) & 1, (kt + 1) * BK);
            cp_wait<1>();
        } else {
            cp_wait<0>();
        }
        __syncthreads();

        const float* ab = sm + (kt & 1) * BUF_FLOATS;
        const float* bb = ab + TILE_FLOATS;

#pragma unroll
        for (int ks = 0; ks < 4; ks++) {
            const int k0 = ks * 8;
            uint32_t aF[4][4], bF[4][2];
#pragma unroll
            for (int mt = 0; mt < 4; mt++) {
                const int r0 = warp_m + mt * 16 + groupID;
                aF[mt][0] = f2tf32(ab[r0 * ROWPAD + k0 + tig]);
                aF[mt][1] = f2tf32(ab[(r0 + 8) * ROWPAD + k0 + tig]);
                aF[mt][2] = f2tf32(ab[r0 * ROWPAD + k0 + tig + 4]);
                aF[mt][3] = f2tf32(ab[(r0 + 8) * ROWPAD + k0 + tig + 4]);
            }
#pragma unroll
            for (int nt = 0; nt < 4; nt++) {
                const int n0 = warp_n + nt * 8 + groupID;
                bF[nt][0] = f2tf32(bb[n0 * ROWPAD + k0 + tig]);
                bF[nt][1] = f2tf32(bb[n0 * ROWPAD + k0 + tig + 4]);
            }
#pragma unroll
            for (int mt = 0; mt < 4; mt++)
#pragma unroll
                for (int nt = 0; nt < 4; nt++)
                    mma_tf32_16n8k8(acc[mt][nt], aF[mt], bF[nt]);
        }
        __syncthreads();
    }

    // Epilogue
#pragma unroll
    for (int mt = 0; mt < 4; mt++) {
#pragma unroll
        for (int nt = 0; nt < 4; nt++) {
            const int col = colBase + warp_n + nt * 8 + tig * 2;
            const int row0 = rowBase + warp_m + mt * 16 + groupID;
            const float b0 = bias[col], b1 = bias[col + 1];
            if (MODE == 0) {
                float2 v0 = { acc[mt][nt][0] + b0, acc[mt][nt][1] + b1 };
                float2 v1 = { acc[mt][nt][2] + b0, acc[mt][nt][3] + b1 };
                *(float2*)(C + (size_t)row0 * N + col) = v0;
                *(float2*)(C + (size_t)(row0 + 8) * N + col) = v1;
            } else {
                const int which = col >> 10;
                const int rem = col & 1023;
                const int h = rem >> 6, dk0 = rem & 63;
                float* dst = (which == 0) ? g_q : (which == 1) ? g_k : g_v;
                const float sc = (which == 0) ? 0.125f : 1.0f;
                const int bb0 = row0 >> 11, l0 = row0 & (NL - 1);
                const int bb1 = (row0 + 8) >> 11, l1 = (row0 + 8) & (NL - 1);
                float2 v0 = { (acc[mt][nt][0] + b0) * sc, (acc[mt][nt][1] + b1) * sc };
                float2 v1 = { (acc[mt][nt][2] + b0) * sc, (acc[mt][nt][3] + b1) * sc };
                *(float2*)(dst + (((size_t)(bb0 * NH + h) * NL + l0) * NDK + dk0)) = v0;
                *(float2*)(dst + (((size_t)(bb1 * NH + h) * NL + l1) * NDK + dk0)) = v1;
            }
        }
    }
}

// ---------------------------------------------------------------------------
// Fused attention (unchanged, verified in R1): per (b,h), 64-query tiles,
// streaming over 64-key tiles, reference-exact masked softmax semantics.
// ---------------------------------------------------------------------------
constexpr int SMEM_ATTN_BYTES = (3 * 64 * 68 + 64 * 65) * 4;  // 68864 B

__global__ __launch_bounds__(256) void attn_kernel(const int* __restrict__ mask)
{
    extern __shared__ float smf[];
    float* Qs = smf;                // [64][68]
    float* Ks = Qs + 64 * 68;       // [64][68]
    float* Vs = Ks + 64 * 68;       // [64][68]
    float* Ps = Vs + 64 * 68;       // [64][65]

    const int tid = threadIdx.x;
    const int qi = tid >> 2;
    const int t  = tid & 3;

    const int qt = blockIdx.x;
    const int bh = blockIdx.y;
    const int b  = bh >> 4;
    const int h  = bh & 15;
    const int q0 = qt * 64;

    const float* Qg = g_q + ((size_t)bh * NL + q0) * NDK;
    const float* Kg = g_k + (size_t)bh * NL * NDK;
    const float* Vg = g_v + (size_t)bh * NL * NDK;
    const int* mrow = mask + ((size_t)b * NL + (q0 + qi)) * NL;

#pragma unroll
    for (int v = 0; v < 4; v++) {
        const int lin = tid + v * 256;
        const int r = lin >> 4;
        const int c = (lin & 15) * 4;
        float4 x = *(const float4*)(Qg + r * 64 + c);
        float* d = Qs + r * 68 + c;
        d[0] = x.x; d[1] = x.y; d[2] = x.z; d[3] = x.w;
    }

    float acc[16];
#pragma unroll
    for (int i = 0; i < 16; i++) acc[i] = 0.0f;
    float m_run = -1e30f;
    float d_run = 0.0f;

    for (int kt = 0; kt < NL / 64; kt++) {
        const int k0 = kt * 64;
#pragma unroll
        for (int v = 0; v < 4; v++) {
            const int lin = tid + v * 256;
            const int r = lin >> 4;
            const int c = (lin & 15) * 4;
            float4 kx = *(const float4*)(Kg + (size_t)(k0 + r) * 64 + c);
            float4 vx = *(const float4*)(Vg + (size_t)(k0 + r) * 64 + c);
            float* dk = Ks + r * 68 + c;
            float* dv = Vs + r * 68 + c;
            dk[0] = kx.x; dk[1] = kx.y; dk[2] = kx.z; dk[3] = kx.w;
            dv[0] = vx.x; dv[1] = vx.y; dv[2] = vx.z; dv[3] = vx.w;
        }
        __syncthreads();

        float s[16];
#pragma unroll
        for (int j = 0; j < 16; j++) s[j] = 0.0f;
#pragma unroll 4
        for (int d4 = 0; d4 < 16; d4++) {
            float4 q4 = *(const float4*)&Qs[qi * 68 + d4 * 4];
#pragma unroll
            for (int j = 0; j < 16; j++) {
                const int kj = 4 * j + t;
                float4 k4 = *(const float4*)&Ks[kj * 68 + d4 * 4];
                s[j] = fmaf(q4.x, k4.x, s[j]);
                s[j] = fmaf(q4.y, k4.y, s[j]);
                s[j] = fmaf(q4.z, k4.z, s[j]);
                s[j] = fmaf(q4.w, k4.w, s[j]);
            }
        }

        const int* mp = mrow + k0;
        int mv[16];
        float vals[16];
        float tmax = -1e30f;
#pragma unroll
        for (int j = 0; j < 16; j++) {
            mv[j] = mp[4 * j + t];
            vals[j] = mv[j] ? s[j] : 0.0f;
            tmax = fmaxf(tmax, vals[j]);
        }
        tmax = fmaxf(tmax, __shfl_xor_sync(0xffffffffu, tmax, 1));
        tmax = fmaxf(tmax, __shfl_xor_sync(0xffffffffu, tmax, 2));
        const float m_new = fmaxf(m_run, tmax);

        float p[16];
        float psum = 0.0f;
#pragma unroll
        for (int j = 0; j < 16; j++) {
            p[j] = __expf(vals[j] - m_new);
            psum += p[j];
        }
        psum += __shfl_xor_sync(0xffffffffu, psum, 1);
        psum += __shfl_xor_sync(0xffffffffu, psum, 2);

        const float corr = __expf(m_run - m_new);
        d_run = d_run * corr + psum;
#pragma unroll
        for (int i = 0; i < 16; i++) acc[i] *= corr;
        m_run = m_new;

#pragma unroll
        for (int j = 0; j < 16; j++)
            Ps[qi * 65 + 4 * j + t] = mv[j] ? p[j] : 0.0f;
        __syncthreads();

#pragma unroll 4
        for (int kj = 0; kj < 64; kj++) {
            const float pw = Ps[qi * 65 + kj];
#pragma unroll
            for (int g = 0; g < 4; g++) {
                float4 v4 = *(const float4*)&Vs[kj * 68 + t * 16 + g * 4];
                acc[g * 4 + 0] = fmaf(pw, v4.x, acc[g * 4 + 0]);
                acc[g * 4 + 1] = fmaf(pw, v4.y, acc[g * 4 + 1]);
                acc[g * 4 + 2] = fmaf(pw, v4.z, acc[g * 4 + 2]);
                acc[g * 4 + 3] = fmaf(pw, v4.w, acc[g * 4 + 3]);
            }
        }
        __syncthreads();
    }

    const float inv = 1.0f / d_run;
    float* op = g_ctx + ((size_t)(b * NL + q0 + qi) * ND) + h * NDK + t * 16;
#pragma unroll
    for (int g = 0; g < 4; g++) {
        float4 o;
        o.x = acc[g * 4 + 0] * inv;
        o.y = acc[g * 4 + 1] * inv;
        o.z = acc[g * 4 + 2] * inv;
        o.w = acc[g * 4 + 3] * inv;
        *(float4*)(op + g * 4) = o;
    }
}

// ---------------------------------------------------------------------------
extern "C" void kernel_launch(void* const* d_in, const int* in_sizes, int n_in,
                              void* d_out, int out_size)
{
    (void)in_sizes; (void)n_in; (void)out_size;
    const float* X    = (const float*)d_in[0];   // (B,L,D)
    const int*   mask = (const int*)d_in[1];     // (B,L,L)
    const float* W1   = (const float*)d_in[2];   // (D,3D)
    const float* b1   = (const float*)d_in[3];   // (3D)
    const float* W2   = (const float*)d_in[4];   // (D,D)
    const float* b2   = (const float*)d_in[5];   // (D)
    float* out = (float*)d_out;                  // (B,L,D)

    void *ctxPtr = nullptr, *w1tPtr = nullptr, *w2tPtr = nullptr;
    cudaGetSymbolAddress(&ctxPtr, g_ctx);
    cudaGetSymbolAddress(&w1tPtr, g_w1t);
    cudaGetSymbolAddress(&w2tPtr, g_w2t);

    cudaFuncSetAttribute(attn_kernel,
                         cudaFuncAttributeMaxDynamicSharedMemorySize,
                         SMEM_ATTN_BYTES);
    cudaFuncSetAttribute(mma_gemm<0>,
                         cudaFuncAttributeMaxDynamicSharedMemorySize,
                         GEMM_SMEM_BYTES);
    cudaFuncSetAttribute(mma_gemm<1>,
                         cudaFuncAttributeMaxDynamicSharedMemorySize,
                         GEMM_SMEM_BYTES);

    // 0) Transpose weights to K-major (N x K) for the mma B operand
    transpose_kernel<<<dim3(NQKV / 32, ND / 32), dim3(32, 8)>>>(
        W1, (float*)w1tPtr, ND, NQKV);
    transpose_kernel<<<dim3(ND / 32, ND / 32), dim3(32, 8)>>>(
        W2, (float*)w2tPtr, ND, ND);

    // 1) QKV projection (TF32 mma.sync) + scatter into g_q/g_k/g_v
    mma_gemm<1><<<dim3(NQKV / 128, MROWS / 128), 256, GEMM_SMEM_BYTES>>>(
        X, (const float*)w1tPtr, b1, nullptr, MROWS, NQKV, ND);

    // 2) Fused masked attention -> g_ctx
    attn_kernel<<<dim3(NL / 64, NB * NH), 256, SMEM_ATTN_BYTES>>>(mask);

    // 3) Output projection (TF32 mma.sync)
    mma_gemm<0><<<dim3(ND / 128, MROWS / 128), 256, GEMM_SMEM_BYTES>>>(
        (const float*)ctxPtr, (const float*)w2tPtr, b2, out, MROWS, ND, ND);
}

// round 5
// speedup vs baseline: 4.7379x; 4.1496x over previous
#include <cuda_runtime.h>
#include <cstdint>

// Problem constants
namespace {
constexpr int NB = 4;          // batch
constexpr int NL = 2048;       // sequence length
constexpr int ND = 1024;       // model dim
constexpr int NH = 16;         // heads
constexpr int NDK = 64;        // head dim
constexpr int MROWS = NB * NL;     // 8192
constexpr int NQKV = 3 * ND;       // 3072
}

// Scratch (device globals: allocation-free per harness rules)
__device__ float g_q[(size_t)NB * NH * NL * NDK];   // (B,H,L,DK), pre-scaled by 1/8
__device__ float g_k[(size_t)NB * NH * NL * NDK];
__device__ float g_v[(size_t)NB * NH * NL * NDK];
__device__ float g_ctx[(size_t)NB * NL * ND];       // (B,L,D)
__device__ float g_w1t[(size_t)NQKV * ND];          // W1^T (3D x D)
__device__ float g_w2t[(size_t)ND * ND];            // W2^T (D x D)

// ---------------------------------------------------------------------------
// Helpers
// ---------------------------------------------------------------------------
__device__ __forceinline__ uint32_t f2tf32(float x) {
    uint32_t r;
    asm("cvt.rna.tf32.f32 %0, %1;" : "=r"(r) : "f"(x));
    return r;
}
__device__ __forceinline__ void cp_async16(uint32_t saddr, const void* g) {
    asm volatile("cp.async.cg.shared.global [%0], [%1], 16;"
                 :: "r"(saddr), "l"(g));
}
__device__ __forceinline__ void cp_commit() {
    asm volatile("cp.async.commit_group;");
}
template <int N>
__device__ __forceinline__ void cp_wait() {
    asm volatile("cp.async.wait_group %0;" :: "n"(N));
}
__device__ __forceinline__ void mma_tf32_16n8k8(float* c, const uint32_t* a,
                                                const uint32_t* b) {
    asm volatile(
        "mma.sync.aligned.m16n8k8.row.col.f32.tf32.tf32.f32 "
        "{%0,%1,%2,%3}, {%4,%5,%6,%7}, {%8,%9}, {%0,%1,%2,%3};"
        : "+f"(c[0]), "+f"(c[1]), "+f"(c[2]), "+f"(c[3])
        : "r"(a[0]), "r"(a[1]), "r"(a[2]), "r"(a[3]), "r"(b[0]), "r"(b[1]));
}

// ---------------------------------------------------------------------------
// Transpose kernel: dst[c][r] = src[r][c], R x C -> C x R
// ---------------------------------------------------------------------------
__global__ void transpose_kernel(const float* __restrict__ src,
                                 float* __restrict__ dst, int R, int C) {
    __shared__ float t[32][33];
    const int c0 = blockIdx.x * 32, r0 = blockIdx.y * 32;
    const int x = threadIdx.x, y = threadIdx.y;  // 32 x 8
#pragma unroll
    for (int i = 0; i < 32; i += 8)
        t[y + i][x] = src[(size_t)(r0 + y + i) * C + c0 + x];
    __syncthreads();
#pragma unroll
    for (int i = 0; i < 32; i += 8)
        dst[(size_t)(c0 + y + i) * R + r0 + x] = t[x][y + i];
}

// ---------------------------------------------------------------------------
// TF32 mma.sync GEMM (unchanged from R4, verified): D = A @ Bt^T + bias
// ---------------------------------------------------------------------------
constexpr int BK = 32;
constexpr int ROWPAD = 36;
constexpr int TILE_FLOATS = 128 * ROWPAD;
constexpr int BUF_FLOATS = 2 * TILE_FLOATS;
constexpr int GEMM_SMEM_BYTES = 2 * BUF_FLOATS * 4;   // 73728

template <int MODE>
__global__ __launch_bounds__(256)
void mma_gemm(const float* __restrict__ A, const float* __restrict__ Bt,
              const float* __restrict__ bias, float* __restrict__ C,
              int M, int N, int K)
{
    extern __shared__ float sm[];

    const int tid = threadIdx.x;
    const int wid = tid >> 5, lane = tid & 31;
    const int groupID = lane >> 2, tig = lane & 3;
    const int warp_m = (wid & 1) * 64;
    const int warp_n = (wid >> 1) * 32;
    const int rowBase = blockIdx.y * 128, colBase = blockIdx.x * 128;

    const uint32_t smem_base = (uint32_t)__cvta_generic_to_shared(sm);

    auto issue_chunk = [&](int buf, int k0) {
        const uint32_t a_s = smem_base + (uint32_t)(buf * BUF_FLOATS) * 4u;
        const uint32_t b_s = a_s + (uint32_t)TILE_FLOATS * 4u;
#pragma unroll
        for (int i = 0; i < 4; i++) {
            const int lin = tid + i * 256;
            const int r = lin >> 3, c = (lin & 7) * 4;
            const uint32_t so = (uint32_t)(r * ROWPAD + c) * 4u;
            cp_async16(a_s + so, A + (size_t)(rowBase + r) * K + k0 + c);
            cp_async16(b_s + so, Bt + (size_t)(colBase + r) * K + k0 + c);
        }
        cp_commit();
    };

    float acc[4][4][4];
#pragma unroll
    for (int mt = 0; mt < 4; mt++)
#pragma unroll
        for (int nt = 0; nt < 4; nt++)
#pragma unroll
            for (int i = 0; i < 4; i++) acc[mt][nt][i] = 0.0f;

    const int NK = K / BK;
    issue_chunk(0, 0);

    for (int kt = 0; kt < NK; kt++) {
        if (kt + 1 < NK) {
            issue_chunk((kt + 1) & 1, (kt + 1) * BK);
            cp_wait<1>();
        } else {
            cp_wait<0>();
        }
        __syncthreads();

        const float* ab = sm + (kt & 1) * BUF_FLOATS;
        const float* bb = ab + TILE_FLOATS;

#pragma unroll
        for (int ks = 0; ks < 4; ks++) {
            const int k0 = ks * 8;
            uint32_t aF[4][4], bF[4][2];
#pragma unroll
            for (int mt = 0; mt < 4; mt++) {
                const int r0 = warp_m + mt * 16 + groupID;
                aF[mt][0] = f2tf32(ab[r0 * ROWPAD + k0 + tig]);
                aF[mt][1] = f2tf32(ab[(r0 + 8) * ROWPAD + k0 + tig]);
                aF[mt][2] = f2tf32(ab[r0 * ROWPAD + k0 + tig + 4]);
                aF[mt][3] = f2tf32(ab[(r0 + 8) * ROWPAD + k0 + tig + 4]);
            }
#pragma unroll
            for (int nt = 0; nt < 4; nt++) {
                const int n0 = warp_n + nt * 8 + groupID;
                bF[nt][0] = f2tf32(bb[n0 * ROWPAD + k0 + tig]);
                bF[nt][1] = f2tf32(bb[n0 * ROWPAD + k0 + tig + 4]);
            }
#pragma unroll
            for (int mt = 0; mt < 4; mt++)
#pragma unroll
                for (int nt = 0; nt < 4; nt++)
                    mma_tf32_16n8k8(acc[mt][nt], aF[mt], bF[nt]);
        }
        __syncthreads();
    }

#pragma unroll
    for (int mt = 0; mt < 4; mt++) {
#pragma unroll
        for (int nt = 0; nt < 4; nt++) {
            const int col = colBase + warp_n + nt * 8 + tig * 2;
            const int row0 = rowBase + warp_m + mt * 16 + groupID;
            const float b0 = bias[col], b1 = bias[col + 1];
            if (MODE == 0) {
                float2 v0 = { acc[mt][nt][0] + b0, acc[mt][nt][1] + b1 };
                float2 v1 = { acc[mt][nt][2] + b0, acc[mt][nt][3] + b1 };
                *(float2*)(C + (size_t)row0 * N + col) = v0;
                *(float2*)(C + (size_t)(row0 + 8) * N + col) = v1;
            } else {
                const int which = col >> 10;
                const int rem = col & 1023;
                const int h = rem >> 6, dk0 = rem & 63;
                float* dst = (which == 0) ? g_q : (which == 1) ? g_k : g_v;
                const float sc = (which == 0) ? 0.125f : 1.0f;
                const int bb0 = row0 >> 11, l0 = row0 & (NL - 1);
                const int bb1 = (row0 + 8) >> 11, l1 = (row0 + 8) & (NL - 1);
                float2 v0 = { (acc[mt][nt][0] + b0) * sc, (acc[mt][nt][1] + b1) * sc };
                float2 v1 = { (acc[mt][nt][2] + b0) * sc, (acc[mt][nt][3] + b1) * sc };
                *(float2*)(dst + (((size_t)(bb0 * NH + h) * NL + l0) * NDK + dk0)) = v0;
                *(float2*)(dst + (((size_t)(bb1 * NH + h) * NL + l1) * NDK + dk0)) = v1;
            }
        }
    }
}

// ---------------------------------------------------------------------------
// Tensorized flash attention (TF32 mma.sync).
// CTA = (b,h) x 128 queries; 8 warps x 16 query rows; stream 64-key tiles.
// Reference-exact mask semantics: val = mask ? s : 0.0; softmax denominator
// over ALL entries; numerator zeroed where masked.
// Smem: Ks[64][68], Vs[64][68], Ps[128][68] (also Q staging).
// ---------------------------------------------------------------------------
constexpr int ATT_SMEM_BYTES = (64 * 68 + 64 * 68 + 128 * 68) * 4;  // 69632

__global__ __launch_bounds__(256, 1)
void attn_mma_kernel(const int* __restrict__ mask)
{
    extern __shared__ float smf[];
    float* Ks = smf;               // [64][68]
    float* Vs = Ks + 64 * 68;      // [64][68]
    float* Ps = Vs + 64 * 68;      // [128][68] (Q staging, then P)

    const int tid = threadIdx.x;
    const int wid = tid >> 5, lane = tid & 31;
    const int g = lane >> 2, t = lane & 3;
    const int wrow = wid * 16;

    const int qt = blockIdx.x;     // 0..15
    const int bh = blockIdx.y;     // 0..63
    const int b = bh >> 4, h = bh & 15;
    const int q0 = qt * 128;

    const float* Qg = g_q + ((size_t)bh * NL + q0) * NDK;
    const float* Kg = g_k + (size_t)bh * NL * NDK;
    const float* Vg = g_v + (size_t)bh * NL * NDK;
    const int* mrow0 = mask + ((size_t)b * NL + (q0 + wrow + g)) * NL;
    const int* mrow1 = mrow0 + 8 * NL;

    // Stage Q (128x64) into Ps
#pragma unroll
    for (int i = 0; i < 8; i++) {
        const int lin = tid + i * 256;        // 2048 float4 slots
        const int r = lin >> 4, c = (lin & 15) * 4;
        float4 x = *(const float4*)(Qg + (size_t)r * NDK + c);
        float* d = Ps + r * 68 + c;
        d[0] = x.x; d[1] = x.y; d[2] = x.z; d[3] = x.w;
    }
    __syncthreads();

    // Extract Q fragments (held in registers for the whole kernel)
    uint32_t qF[8][4];
#pragma unroll
    for (int ks = 0; ks < 8; ks++) {
        const int k0 = ks * 8;
        qF[ks][0] = f2tf32(Ps[(wrow + g) * 68 + k0 + t]);
        qF[ks][1] = f2tf32(Ps[(wrow + g + 8) * 68 + k0 + t]);
        qF[ks][2] = f2tf32(Ps[(wrow + g) * 68 + k0 + t + 4]);
        qF[ks][3] = f2tf32(Ps[(wrow + g + 8) * 68 + k0 + t + 4]);
    }

    float ctx[8][4];
#pragma unroll
    for (int nt = 0; nt < 8; nt++)
#pragma unroll
        for (int i = 0; i < 4; i++) ctx[nt][i] = 0.0f;
    float m0 = -1e30f, m1 = -1e30f, d0 = 0.0f, d1 = 0.0f;

    for (int kt = 0; kt < NL / 64; kt++) {
        const int k0g = kt * 64;
        __syncthreads();   // prior PV reads / Q extraction complete

        // Load K, V tiles (64x64 each, coalesced float4)
#pragma unroll
        for (int i = 0; i < 4; i++) {
            const int lin = tid + i * 256;    // 1024 float4 slots
            const int r = lin >> 4, c = (lin & 15) * 4;
            float4 kx = *(const float4*)(Kg + (size_t)(k0g + r) * NDK + c);
            float4 vx = *(const float4*)(Vg + (size_t)(k0g + r) * NDK + c);
            float* dk = Ks + r * 68 + c;
            float* dv = Vs + r * 68 + c;
            dk[0] = kx.x; dk[1] = kx.y; dk[2] = kx.z; dk[3] = kx.w;
            dv[0] = vx.x; dv[1] = vx.y; dv[2] = vx.z; dv[3] = vx.w;
        }
        __syncthreads();

        // QK^T: scores 16x64 per warp (8 n-tiles of 8 cols)
        float sc[8][4];
#pragma unroll
        for (int nt = 0; nt < 8; nt++) {
            sc[nt][0] = sc[nt][1] = sc[nt][2] = sc[nt][3] = 0.0f;
#pragma unroll
            for (int ks = 0; ks < 8; ks++) {
                const float* kp = Ks + (nt * 8 + g) * 68 + ks * 8 + t;
                uint32_t bF[2] = { f2tf32(kp[0]), f2tf32(kp[4]) };
                mma_tf32_16n8k8(sc[nt], qF[ks], bF);
            }
        }

        // Mask (masked -> 0.0) and row max
        int2 mk0[8], mk1[8];
        float vmax0 = -1e30f, vmax1 = -1e30f;
#pragma unroll
        for (int nt = 0; nt < 8; nt++) {
            const int col = k0g + nt * 8 + 2 * t;
            mk0[nt] = *(const int2*)(mrow0 + col);
            mk1[nt] = *(const int2*)(mrow1 + col);
            sc[nt][0] = mk0[nt].x ? sc[nt][0] : 0.0f;
            sc[nt][1] = mk0[nt].y ? sc[nt][1] : 0.0f;
            sc[nt][2] = mk1[nt].x ? sc[nt][2] : 0.0f;
            sc[nt][3] = mk1[nt].y ? sc[nt][3] : 0.0f;
            vmax0 = fmaxf(vmax0, fmaxf(sc[nt][0], sc[nt][1]));
            vmax1 = fmaxf(vmax1, fmaxf(sc[nt][2], sc[nt][3]));
        }
        vmax0 = fmaxf(vmax0, __shfl_xor_sync(0xffffffffu, vmax0, 1));
        vmax0 = fmaxf(vmax0, __shfl_xor_sync(0xffffffffu, vmax0, 2));
        vmax1 = fmaxf(vmax1, __shfl_xor_sync(0xffffffffu, vmax1, 1));
        vmax1 = fmaxf(vmax1, __shfl_xor_sync(0xffffffffu, vmax1, 2));
        const float mn0 = fmaxf(m0, vmax0);
        const float mn1 = fmaxf(m1, vmax1);

        // exp, denominator sum, numerator (zeroed where masked) -> Ps
        float ps0 = 0.0f, ps1 = 0.0f;
#pragma unroll
        for (int nt = 0; nt < 8; nt++) {
            const float p0 = __expf(sc[nt][0] - mn0);
            const float p1 = __expf(sc[nt][1] - mn0);
            const float p2 = __expf(sc[nt][2] - mn1);
            const float p3 = __expf(sc[nt][3] - mn1);
            ps0 += p0 + p1;
            ps1 += p2 + p3;
            float2 w0 = { mk0[nt].x ? p0 : 0.0f, mk0[nt].y ? p1 : 0.0f };
            float2 w1 = { mk1[nt].x ? p2 : 0.0f, mk1[nt].y ? p3 : 0.0f };
            *(float2*)(Ps + (wrow + g) * 68 + nt * 8 + 2 * t) = w0;
            *(float2*)(Ps + (wrow + g + 8) * 68 + nt * 8 + 2 * t) = w1;
        }
        ps0 += __shfl_xor_sync(0xffffffffu, ps0, 1);
        ps0 += __shfl_xor_sync(0xffffffffu, ps0, 2);
        ps1 += __shfl_xor_sync(0xffffffffu, ps1, 1);
        ps1 += __shfl_xor_sync(0xffffffffu, ps1, 2);

        const float corr0 = __expf(m0 - mn0);
        const float corr1 = __expf(m1 - mn1);
        d0 = d0 * corr0 + ps0;
        d1 = d1 * corr1 + ps1;
        m0 = mn0; m1 = mn1;
#pragma unroll
        for (int nt = 0; nt < 8; nt++) {
            ctx[nt][0] *= corr0; ctx[nt][1] *= corr0;
            ctx[nt][2] *= corr1; ctx[nt][3] *= corr1;
        }
        __syncwarp();   // P stores visible to sibling lanes

        // PV: ctx(16x64) += P(16x64) @ V(64x64)
#pragma unroll
        for (int ks = 0; ks < 8; ks++) {
            const int k0 = ks * 8;
            uint32_t aP[4];
            aP[0] = f2tf32(Ps[(wrow + g) * 68 + k0 + t]);
            aP[1] = f2tf32(Ps[(wrow + g + 8) * 68 + k0 + t]);
            aP[2] = f2tf32(Ps[(wrow + g) * 68 + k0 + t + 4]);
            aP[3] = f2tf32(Ps[(wrow + g + 8) * 68 + k0 + t + 4]);
#pragma unroll
            for (int nt = 0; nt < 8; nt++) {
                uint32_t bF[2] = {
                    f2tf32(Vs[(k0 + t) * 68 + nt * 8 + g]),
                    f2tf32(Vs[(k0 + t + 4) * 68 + nt * 8 + g])
                };
                mma_tf32_16n8k8(ctx[nt], aP, bF);
            }
        }
    }

    // Epilogue: scale by 1/d, write to g_ctx (B,L,D) at head offset
    const float inv0 = 1.0f / d0;
    const float inv1 = 1.0f / d1;
    const int l0 = q0 + wrow + g;
    const int l1 = l0 + 8;
    float* o0 = g_ctx + ((size_t)(b * NL + l0)) * ND + h * NDK;
    float* o1 = g_ctx + ((size_t)(b * NL + l1)) * ND + h * NDK;
#pragma unroll
    for (int nt = 0; nt < 8; nt++) {
        const int dk = nt * 8 + 2 * t;
        float2 v0 = { ctx[nt][0] * inv0, ctx[nt][1] * inv0 };
        float2 v1 = { ctx[nt][2] * inv1, ctx[nt][3] * inv1 };
        *(float2*)(o0 + dk) = v0;
        *(float2*)(o1 + dk) = v1;
    }
}

// ---------------------------------------------------------------------------
extern "C" void kernel_launch(void* const* d_in, const int* in_sizes, int n_in,
                              void* d_out, int out_size)
{
    (void)in_sizes; (void)n_in; (void)out_size;
    const float* X    = (const float*)d_in[0];   // (B,L,D)
    const int*   mask = (const int*)d_in[1];     // (B,L,L)
    const float* W1   = (const float*)d_in[2];   // (D,3D)
    const float* b1   = (const float*)d_in[3];   // (3D)
    const float* W2   = (const float*)d_in[4];   // (D,D)
    const float* b2   = (const float*)d_in[5];   // (D)
    float* out = (float*)d_out;                  // (B,L,D)

    void *ctxPtr = nullptr, *w1tPtr = nullptr, *w2tPtr = nullptr;
    cudaGetSymbolAddress(&ctxPtr, g_ctx);
    cudaGetSymbolAddress(&w1tPtr, g_w1t);
    cudaGetSymbolAddress(&w2tPtr, g_w2t);

    cudaFuncSetAttribute(attn_mma_kernel,
                         cudaFuncAttributeMaxDynamicSharedMemorySize,
                         ATT_SMEM_BYTES);
    cudaFuncSetAttribute(mma_gemm<0>,
                         cudaFuncAttributeMaxDynamicSharedMemorySize,
                         GEMM_SMEM_BYTES);
    cudaFuncSetAttribute(mma_gemm<1>,
                         cudaFuncAttributeMaxDynamicSharedMemorySize,
                         GEMM_SMEM_BYTES);

    // 0) Transpose weights to K-major (N x K) for the mma B operand
    transpose_kernel<<<dim3(NQKV / 32, ND / 32), dim3(32, 8)>>>(
        W1, (float*)w1tPtr, ND, NQKV);
    transpose_kernel<<<dim3(ND / 32, ND / 32), dim3(32, 8)>>>(
        W2, (float*)w2tPtr, ND, ND);

    // 1) QKV projection (TF32 mma.sync) + scatter into g_q/g_k/g_v
    mma_gemm<1><<<dim3(NQKV / 128, MROWS / 128), 256, GEMM_SMEM_BYTES>>>(
        X, (const float*)w1tPtr, b1, nullptr, MROWS, NQKV, ND);

    // 2) Tensorized flash attention -> g_ctx
    attn_mma_kernel<<<dim3(NL / 128, NB * NH), 256, ATT_SMEM_BYTES>>>(mask);

    // 3) Output projection (TF32 mma.sync)
    mma_gemm<0><<<dim3(ND / 128, MROWS / 128), 256, GEMM_SMEM_BYTES>>>(
        (const float*)ctxPtr, (const float*)w2tPtr, b2, out, MROWS, ND, ND);
}